// round 1
// baseline (speedup 1.0000x reference)
#include <cuda_runtime.h>

// Shapes (fixed by the problem): streams [B=4, N=8, T=2048, D=1024] fp32,
// logits [8,8] fp32. out[b,i,t,d] = sum_j H[i,j] * streams[b,j,t,d],
// H = sinkhorn_doubly_stochastic(logits / temp), temp = 1.0.

#define NS        8
#define SINK_ITERS 20
#define SINK_EPS  1e-8f
#define B_DIM     4
#define TD        (2048 * 1024)       // elements per (b, j) slice
#define TD4       (TD / 4)            // float4 per slice = 524288 = 1<<19
#define TD4_LOG2  19

// Scratch for the mixing matrix (device-global: no allocs allowed).
__device__ float d_H[NS * NS];

// ---------------------------------------------------------------------------
// Kernel 1: Sinkhorn on the 8x8 logits. Tiny — one thread does everything.
// Matches the reference exactly: rowmax-sub, exp()+eps, then 20 iterations of
// row-normalize (sum+eps) followed by col-normalize (sum+eps).
// ---------------------------------------------------------------------------
__global__ void sinkhorn_kernel(const float* __restrict__ logits) {
    if (threadIdx.x != 0 || blockIdx.x != 0) return;

    float p[NS * NS];
    // x = logits - rowmax; p = exp(x) + eps   (temperature = 1.0)
    #pragma unroll
    for (int i = 0; i < NS; i++) {
        float m = -1e30f;
        #pragma unroll
        for (int j = 0; j < NS; j++) m = fmaxf(m, logits[i * NS + j]);
        #pragma unroll
        for (int j = 0; j < NS; j++)
            p[i * NS + j] = expf(logits[i * NS + j] - m) + SINK_EPS;
    }

    for (int it = 0; it < SINK_ITERS; it++) {
        // row normalize
        #pragma unroll
        for (int i = 0; i < NS; i++) {
            float s = 0.f;
            #pragma unroll
            for (int j = 0; j < NS; j++) s += p[i * NS + j];
            float inv = 1.0f / (s + SINK_EPS);
            #pragma unroll
            for (int j = 0; j < NS; j++) p[i * NS + j] *= inv;
        }
        // col normalize
        #pragma unroll
        for (int j = 0; j < NS; j++) {
            float s = 0.f;
            #pragma unroll
            for (int i = 0; i < NS; i++) s += p[i * NS + j];
            float inv = 1.0f / (s + SINK_EPS);
            #pragma unroll
            for (int i = 0; i < NS; i++) p[i * NS + j] *= inv;
        }
    }

    #pragma unroll
    for (int k = 0; k < NS * NS; k++) d_H[k] = p[k];
}

// ---------------------------------------------------------------------------
// Kernel 2: the mix. One thread per float4 position (b, td4). Reads the 8
// j-slices once (stride TD4 float4 = 2 MB), produces all 8 outputs.
// Total traffic = 256 MB read + 256 MB write (the HBM minimum).
// ---------------------------------------------------------------------------
__global__ void __launch_bounds__(256)
mix_kernel(const float4* __restrict__ in, float4* __restrict__ out) {
    __shared__ float sH[NS * NS];
    if (threadIdx.x < NS * NS) sH[threadIdx.x] = d_H[threadIdx.x];
    __syncthreads();

    int pos = blockIdx.x * blockDim.x + threadIdx.x;   // [0, B*TD4)
    int b = pos >> TD4_LOG2;
    int r = pos & (TD4 - 1);
    int base = b * (NS * TD4) + r;                     // max ~16.8M float4: fits int

    float4 v[NS];
    #pragma unroll
    for (int j = 0; j < NS; j++) v[j] = in[base + j * TD4];

    #pragma unroll
    for (int i = 0; i < NS; i++) {
        float4 a = make_float4(0.f, 0.f, 0.f, 0.f);
        #pragma unroll
        for (int j = 0; j < NS; j++) {
            float h = sH[i * NS + j];
            a.x = fmaf(h, v[j].x, a.x);
            a.y = fmaf(h, v[j].y, a.y);
            a.z = fmaf(h, v[j].z, a.z);
            a.w = fmaf(h, v[j].w, a.w);
        }
        out[base + i * TD4] = a;
    }
}

extern "C" void kernel_launch(void* const* d_in, const int* in_sizes, int n_in,
                              void* d_out, int out_size) {
    const float* streams = (const float*)d_in[0];   // [4, 8, 2048, 1024] fp32
    const float* logits  = (const float*)d_in[1];   // [8, 8] fp32
    float* out = (float*)d_out;

    sinkhorn_kernel<<<1, 32>>>(logits);

    const int total4 = B_DIM * TD4;                 // 2,097,152 threads
    const int threads = 256;
    mix_kernel<<<total4 / threads, threads>>>((const float4*)streams,
                                              (float4*)out);
}

// round 2
// speedup vs baseline: 1.1592x; 1.1592x over previous
#include <cuda_runtime.h>

// streams [B=4, N=8, T=2048, D=1024] fp32, logits [8,8] fp32.
// out[b,i,t,d] = sum_j H[i,j] * streams[b,j,t,d], H = sinkhorn(logits), temp=1.

#define NS         8
#define SINK_ITERS 20
#define SINK_EPS   1e-8f
#define B_DIM      4
#define TD         (2048 * 1024)      // elements per (b, j) slice
#define TD4        (TD / 4)           // float4 per slice = 1<<19
#define TD4_LOG2   19

__device__ float d_H[NS * NS];

// ---------------------------------------------------------------------------
// Kernel 1: warp-parallel Sinkhorn on the 8x8 logits.
// Lane l owns elements e0 = (row=l>>3, col=l&7) and e1 = (row+4, col).
//   row reduction: shfl_xor 1,2,4 (within each 8-lane row group), per register
//   col reduction: e0 and e1 share a column -> c = e0+e1, shfl_xor 8,16
// ---------------------------------------------------------------------------
__global__ void sinkhorn_kernel(const float* __restrict__ logits) {
    const unsigned FULL = 0xFFFFFFFFu;
    int lane = threadIdx.x;            // 0..31
    float x0 = logits[lane];           // rows 0-3
    float x1 = logits[lane + 32];      // rows 4-7

    // row max (over the 8 lanes of each row)
    float m0 = x0, m1 = x1;
    #pragma unroll
    for (int m = 1; m <= 4; m <<= 1) {
        m0 = fmaxf(m0, __shfl_xor_sync(FULL, m0, m));
        m1 = fmaxf(m1, __shfl_xor_sync(FULL, m1, m));
    }
    float p0 = expf(x0 - m0) + SINK_EPS;
    float p1 = expf(x1 - m1) + SINK_EPS;

    for (int it = 0; it < SINK_ITERS; it++) {
        // row normalize
        float s0 = p0, s1 = p1;
        #pragma unroll
        for (int m = 1; m <= 4; m <<= 1) {
            s0 += __shfl_xor_sync(FULL, s0, m);
            s1 += __shfl_xor_sync(FULL, s1, m);
        }
        p0 = p0 / (s0 + SINK_EPS);
        p1 = p1 / (s1 + SINK_EPS);

        // col normalize (e0,e1 are same column, rows r and r+4)
        float c = p0 + p1;
        c += __shfl_xor_sync(FULL, c, 8);
        c += __shfl_xor_sync(FULL, c, 16);
        float inv = 1.0f / (c + SINK_EPS);
        p0 *= inv;
        p1 *= inv;
    }

    d_H[lane]      = p0;
    d_H[lane + 32] = p1;
}

// ---------------------------------------------------------------------------
// Kernel 2: the mix. One thread per float4 position (b, td4). Reads the 8
// j-slices once (streaming), produces all 8 outputs. 256MB read + 256MB write.
// ---------------------------------------------------------------------------
__global__ void __launch_bounds__(256)
mix_kernel(const float4* __restrict__ in, float4* __restrict__ out) {
    __shared__ float sH[NS * NS];
    if (threadIdx.x < NS * NS) sH[threadIdx.x] = d_H[threadIdx.x];
    __syncthreads();

    int pos = blockIdx.x * blockDim.x + threadIdx.x;   // [0, B*TD4)
    int b = pos >> TD4_LOG2;
    int r = pos & (TD4 - 1);
    int base = b * (NS * TD4) + r;

    float4 v[NS];
    #pragma unroll
    for (int j = 0; j < NS; j++) v[j] = __ldcs(&in[base + j * TD4]);

    #pragma unroll
    for (int i = 0; i < NS; i++) {
        float4 a = make_float4(0.f, 0.f, 0.f, 0.f);
        #pragma unroll
        for (int j = 0; j < NS; j++) {
            float h = sH[i * NS + j];
            a.x = fmaf(h, v[j].x, a.x);
            a.y = fmaf(h, v[j].y, a.y);
            a.z = fmaf(h, v[j].z, a.z);
            a.w = fmaf(h, v[j].w, a.w);
        }
        __stcs(&out[base + i * TD4], a);
    }
}

extern "C" void kernel_launch(void* const* d_in, const int* in_sizes, int n_in,
                              void* d_out, int out_size) {
    const float* streams = (const float*)d_in[0];
    const float* logits  = (const float*)d_in[1];
    float* out = (float*)d_out;

    sinkhorn_kernel<<<1, 32>>>(logits);

    const int total4 = B_DIM * TD4;
    const int threads = 256;
    mix_kernel<<<total4 / threads, threads>>>((const float4*)streams,
                                              (float4*)out);
}